// round 1
// baseline (speedup 1.0000x reference)
#include <cuda_runtime.h>
#include <math.h>

#define NMB  4
#define CNUM 17
#define HNUM 8
#define BNUM 8
#define SLEN 512
#define DDIM 64
#define TI   64          // rows per block
#define JT   128         // j chunk per class pass
#define KSTR 68          // Ks row stride (floats), conflict-free, 16B aligned
#define USTR 320         // Us row stride = 5*64

// Premixed W1_: [C][h][m][n]
__device__ float g_W[CNUM * HNUM * DDIM * DDIM];

// ---------------- Kernel 1: W1_[c,h] = sum_B softmax(alpha1,axis=B)[c,B,h] * W1[B,h] ----
__global__ void wmix_kernel(const float* __restrict__ W1,
                            const float* __restrict__ alpha1) {
    int c = blockIdx.x;   // 0..16
    int h = blockIdx.y;   // 0..7
    float a[NMB];
#pragma unroll
    for (int B = 0; B < NMB; B++) a[B] = alpha1[(c * NMB + B) * HNUM + h];
    float mx = fmaxf(fmaxf(a[0], a[1]), fmaxf(a[2], a[3]));
    float w[NMB], s = 0.f;
#pragma unroll
    for (int B = 0; B < NMB; B++) { w[B] = __expf(a[B] - mx); s += w[B]; }
    float inv = 1.f / s;
#pragma unroll
    for (int B = 0; B < NMB; B++) w[B] *= inv;

    float* dst = g_W + (c * HNUM + h) * DDIM * DDIM;
    const float* src = W1 + h * DDIM * DDIM;           // [B][h][e], B stride = HNUM*4096
    for (int e = threadIdx.x; e < DDIM * DDIM; e += blockDim.x) {
        float v = 0.f;
#pragma unroll
        for (int B = 0; B < NMB; B++) v += w[B] * src[B * HNUM * DDIM * DDIM + e];
        dst[e] = v;
    }
}

// ---------------- Kernel 2: fused scores ----------------
// Block = (i-tile of 64 rows, h, b). 256 threads.
// Phase A: U[i][bj][n] = sum_m Q[i][m] * W1_[c(bi,bj)][m][n]   (bj=0..4; slot0 = c=0)
// Phase B: columns grouped by class t; scores[i,j] = U[i][sel]·k_j, sel=(bi==0||t==0)?0:t

// shared layout (bytes):
#define OFF_QS   0                         // 4096 f
#define OFF_US   (16384)                   // 64*USTR f = 81920 B
#define OFF_KS   (16384 + 81920)           // 128*KSTR f = 34816 B
#define OFF_INT  (OFF_KS + 34816)
// ints: bj_all[512], jperm[512], jcnt[8], joff[8], jpos[8], rcnt[8], rlist[256]
#define SMEM_BYTES (OFF_INT + (512 + 512 + 8 + 8 + 8 + 8 + 256) * 4)

__global__ __launch_bounds__(256, 1)
void mb_scores_kernel(const float* __restrict__ q,
                      const float* __restrict__ k,
                      const int*   __restrict__ bseq,
                      float* __restrict__ out) {
    extern __shared__ unsigned char smraw[];
    float* Qs = (float*)(smraw + OFF_QS);
    float* Us = (float*)(smraw + OFF_US);
    float* Ks = (float*)(smraw + OFF_KS);
    int*   bj_all = (int*)(smraw + OFF_INT);
    int*   jperm  = bj_all + 512;
    int*   jcnt   = jperm + 512;
    int*   joff   = jcnt + 8;
    int*   jpos   = joff + 8;
    int*   rcnt   = jpos + 8;
    int*   rlist  = rcnt + 8;

    const int tid = threadIdx.x;
    const int it  = blockIdx.x;
    const int h   = blockIdx.y;
    const int b   = blockIdx.z;
    const int i0  = it * TI;

    const float* qbase = q + ((size_t)(b * HNUM + h) * SLEN + i0) * DDIM;
    const float* kbase = k + ((size_t)(b * HNUM + h) * SLEN) * DDIM;

    // load Q tile (64x64) as float4
    for (int t = tid; t < TI * DDIM / 4; t += 256)
        ((float4*)Qs)[t] = ((const float4*)qbase)[t];
    // load b_seq row
    for (int t = tid; t < SLEN; t += 256) bj_all[t] = bseq[b * SLEN + t];
    if (tid < 8) { jcnt[tid] = 0; rcnt[tid] = 0; }
    __syncthreads();

    // column class histogram
    for (int t = tid; t < SLEN; t += 256) atomicAdd(&jcnt[bj_all[t]], 1);
    __syncthreads();
    if (tid == 0) {
        int s = 0;
        for (int t = 0; t < 5; t++) { joff[t] = s; jpos[t] = s; s += jcnt[t]; }
    }
    __syncthreads();
    // column permutation grouped by class
    for (int t = tid; t < SLEN; t += 256) {
        int c = bj_all[t];
        int p = atomicAdd(&jpos[c], 1);
        jperm[p] = t;
    }
    // row lists for classes 1..4
    for (int t = tid; t < TI; t += 256) {
        int c = bj_all[i0 + t];
        if (c > 0) { int p = atomicAdd(&rcnt[c - 1], 1); rlist[(c - 1) * 64 + p] = t; }
    }
    __syncthreads();

    // ---------------- Phase A ----------------
    {
        // class 0: all 64 rows, slot bj=0, W = W1_[0][h]
        int n = tid & 63, g = tid >> 6;   // g in 0..3 -> 16 rows each
        const float* W0 = g_W + (size_t)h * DDIM * DDIM + n;   // c=0
        float w[DDIM];
#pragma unroll
        for (int m = 0; m < DDIM; m++) w[m] = W0[m * DDIM];
        for (int r = 0; r < 16; r++) {
            int i = g * 16 + r;
            const float4* q4 = (const float4*)(Qs + i * DDIM);
            float acc = 0.f;
#pragma unroll
            for (int mb = 0; mb < 16; mb++) {
                float4 v = q4[mb];
                acc += v.x * w[4*mb] + v.y * w[4*mb+1] + v.z * w[4*mb+2] + v.w * w[4*mb+3];
            }
            Us[i * USTR + n] = acc;
        }
    }
    // classes t=1..4: rows with bi==t fill slots bj=1..4 with W1_[4(t-1)+bj][h]
    for (int t = 1; t <= 4; t++) {
        int cnt = rcnt[t - 1];
        if (cnt == 0) continue;
        int n  = tid & 63;
        int bj = (tid >> 6) + 1;                   // 1..4
        int c  = 4 * (t - 1) + bj;                 // 1..16
        const float* Wc = g_W + (size_t)(c * HNUM + h) * DDIM * DDIM + n;
        float w[DDIM];
#pragma unroll
        for (int m = 0; m < DDIM; m++) w[m] = Wc[m * DDIM];
        for (int r = 0; r < cnt; r++) {
            int i = rlist[(t - 1) * 64 + r];
            const float4* q4 = (const float4*)(Qs + i * DDIM);
            float acc = 0.f;
#pragma unroll
            for (int mb = 0; mb < 16; mb++) {
                float4 v = q4[mb];
                acc += v.x * w[4*mb] + v.y * w[4*mb+1] + v.z * w[4*mb+2] + v.w * w[4*mb+3];
            }
            Us[i * USTR + bj * DDIM + n] = acc;
        }
    }

    // ---------------- Phase B ----------------
    const int tx = tid & 31, ty = tid >> 5;   // 32 x 8
    float* outbase = out + ((size_t)(b * HNUM + h) * SLEN + i0) * SLEN;

    for (int t = 0; t < 5; t++) {
        int nt  = jcnt[t];
        int off = joff[t];
        if (nt == 0) continue;
        for (int j0 = 0; j0 < nt; j0 += JT) {
            int chunk = nt - j0; if (chunk > JT) chunk = JT;
            __syncthreads();   // Ks reuse safety + first iter: Us ready
            // gather K chunk rows (coalesced 256B rows)
            for (int x = tid; x < JT * 16; x += 256) {
                int r = x >> 4, mb = x & 15;
                float4 v;
                if (r < chunk) v = ((const float4*)(kbase + (size_t)jperm[off + j0 + r] * DDIM))[mb];
                else           v = make_float4(0.f, 0.f, 0.f, 0.f);
                *(float4*)(Ks + r * KSTR + mb * 4) = v;
            }
            __syncthreads();

            // register tile: 8 rows (stride 8) x 4 cols (stride 32)
            float acc[8][4];
#pragma unroll
            for (int ii = 0; ii < 8; ii++)
#pragma unroll
                for (int jj = 0; jj < 4; jj++) acc[ii][jj] = 0.f;

            const float* Arow[8];
#pragma unroll
            for (int ii = 0; ii < 8; ii++) {
                int i  = ty + ii * 8;
                int bi = bj_all[i0 + i];
                int sel = (bi == 0 || t == 0) ? 0 : t;
                Arow[ii] = Us + i * USTR + sel * DDIM;
            }
#pragma unroll
            for (int mb = 0; mb < 16; mb++) {
                float4 kv[4];
#pragma unroll
                for (int jj = 0; jj < 4; jj++)
                    kv[jj] = *(const float4*)(Ks + (tx + jj * 32) * KSTR + mb * 4);
#pragma unroll
                for (int ii = 0; ii < 8; ii++) {
                    float4 av = *(const float4*)(Arow[ii] + mb * 4);
#pragma unroll
                    for (int jj = 0; jj < 4; jj++) {
                        acc[ii][jj] += av.x * kv[jj].x;
                        acc[ii][jj] += av.y * kv[jj].y;
                        acc[ii][jj] += av.z * kv[jj].z;
                        acc[ii][jj] += av.w * kv[jj].w;
                    }
                }
            }
            // scattered stores (L2 write-coalesced)
#pragma unroll
            for (int jj = 0; jj < 4; jj++) {
                int jc = tx + jj * 32;
                if (j0 + jc < nt) {
                    int jp = jperm[off + j0 + jc];
#pragma unroll
                    for (int ii = 0; ii < 8; ii++)
                        outbase[(size_t)(ty + ii * 8) * SLEN + jp] = acc[ii][jj];
                }
            }
        }
    }
}

// ---------------- launch ----------------
extern "C" void kernel_launch(void* const* d_in, const int* in_sizes, int n_in,
                              void* d_out, int out_size) {
    const float* q      = (const float*)d_in[0];
    const float* kk     = (const float*)d_in[1];
    const int*   bseq   = (const int*)  d_in[2];
    const float* W1     = (const float*)d_in[3];
    const float* alpha1 = (const float*)d_in[4];
    float* out = (float*)d_out;

    static int attr_done = 0;
    (void)attr_done;
    cudaFuncSetAttribute(mb_scores_kernel,
                         cudaFuncAttributeMaxDynamicSharedMemorySize, SMEM_BYTES);

    dim3 g1(CNUM, HNUM);
    wmix_kernel<<<g1, 256>>>(W1, alpha1);

    dim3 g2(SLEN / TI, HNUM, BNUM);   // (8, 8, 8) = 512 blocks
    mb_scores_kernel<<<g2, 256, SMEM_BYTES>>>(q, kk, bseq, out);
}

// round 2
// speedup vs baseline: 1.2471x; 1.2471x over previous
#include <cuda_runtime.h>
#include <math.h>

#define NMB  4
#define CNUM 17
#define HNUM 8
#define BNUM 8
#define SLEN 512
#define DDIM 64
#define TI   64          // rows per block
#define JT   128         // j chunk per class pass
#define KSTR 68          // Ks row stride (floats): 68%32=4 -> conflict-free LDS.128
#define USTRD 68         // U row stride

// Premixed W1_: [C][h][m][n]
__device__ float g_W[CNUM * HNUM * DDIM * DDIM];

// ---- packed f32x2 helpers ----
union F4U  { float4 f4; unsigned long long u[2]; };
union U64F2 { unsigned long long u; float2 f; };

__device__ __forceinline__ void ffma2(unsigned long long& d,
                                      unsigned long long a,
                                      unsigned long long b) {
    asm("fma.rn.f32x2 %0, %1, %2, %0;" : "+l"(d) : "l"(a), "l"(b));
}
__device__ __forceinline__ unsigned long long pack2(float x, float y) {
    unsigned long long r;
    asm("mov.b64 %0, {%1, %2};" : "=l"(r) : "f"(x), "f"(y));
    return r;
}

// ---------------- Kernel 1: W1_[c,h] = sum_B softmax(alpha1,axis=B)[c,B,h] * W1[B,h] ----
__global__ void wmix_kernel(const float* __restrict__ W1,
                            const float* __restrict__ alpha1) {
    int c = blockIdx.x;   // 0..16
    int h = blockIdx.y;   // 0..7
    float a[NMB];
#pragma unroll
    for (int B = 0; B < NMB; B++) a[B] = alpha1[(c * NMB + B) * HNUM + h];
    float mx = fmaxf(fmaxf(a[0], a[1]), fmaxf(a[2], a[3]));
    float w[NMB], s = 0.f;
#pragma unroll
    for (int B = 0; B < NMB; B++) { w[B] = __expf(a[B] - mx); s += w[B]; }
    float inv = 1.f / s;
#pragma unroll
    for (int B = 0; B < NMB; B++) w[B] *= inv;

    float* dst = g_W + (c * HNUM + h) * DDIM * DDIM;
    const float* src = W1 + h * DDIM * DDIM;
    for (int e = threadIdx.x; e < DDIM * DDIM; e += blockDim.x) {
        float v = 0.f;
#pragma unroll
        for (int B = 0; B < NMB; B++) v += w[B] * src[B * HNUM * DDIM * DDIM + e];
        dst[e] = v;
    }
}

// ---------------- Kernel 2: fused scores ----------------
// shared layout (bytes):
#define OFF_QS   0                           // 16384
#define OFF_U0   16384                       // 64*68*4 = 17408
#define OFF_UT   (16384 + 17408)             // 17408
#define OFF_KS   (OFF_UT + 17408)            // 128*68*4 = 34816
#define OFF_INT  (OFF_KS + 34816)
// ints: bj_all[512], jperm[512], jcnt[8], joff[8], jpos[8], rcnt[8], rlist[256]
#define SMEM_BYTES (OFF_INT + (512 + 512 + 8 + 8 + 8 + 8 + 256) * 4)

__global__ __launch_bounds__(256, 2)
void mb_scores_kernel(const float* __restrict__ q,
                      const float* __restrict__ k,
                      const int*   __restrict__ bseq,
                      float* __restrict__ out) {
    extern __shared__ unsigned char smraw[];
    float* Qs  = (float*)(smraw + OFF_QS);
    float* Us0 = (float*)(smraw + OFF_U0);
    float* Ust = (float*)(smraw + OFF_UT);
    float* Ks  = (float*)(smraw + OFF_KS);
    int*   bj_all = (int*)(smraw + OFF_INT);
    int*   jperm  = bj_all + 512;
    int*   jcnt   = jperm + 512;
    int*   joff   = jcnt + 8;
    int*   jpos   = joff + 8;
    int*   rcnt   = jpos + 8;
    int*   rlist  = rcnt + 8;

    const int tid = threadIdx.x;
    const int it  = blockIdx.x;
    const int h   = blockIdx.y;
    const int b   = blockIdx.z;
    const int i0  = it * TI;

    const float* qbase = q + ((size_t)(b * HNUM + h) * SLEN + i0) * DDIM;
    const float* kbase = k + ((size_t)(b * HNUM + h) * SLEN) * DDIM;

    // load Q tile (64x64) as float4
    for (int t = tid; t < TI * DDIM / 4; t += 256)
        ((float4*)Qs)[t] = ((const float4*)qbase)[t];
    // load b_seq row
    for (int t = tid; t < SLEN; t += 256) bj_all[t] = bseq[b * SLEN + t];
    if (tid < 8) { jcnt[tid] = 0; rcnt[tid] = 0; }
    __syncthreads();

    // column class histogram
    for (int t = tid; t < SLEN; t += 256) atomicAdd(&jcnt[bj_all[t]], 1);
    __syncthreads();
    if (tid == 0) {
        int s = 0;
        for (int t = 0; t < 5; t++) { joff[t] = s; jpos[t] = s; s += jcnt[t]; }
    }
    __syncthreads();
    // column permutation grouped by class
    for (int t = tid; t < SLEN; t += 256) {
        int c = bj_all[t];
        int p = atomicAdd(&jpos[c], 1);
        jperm[p] = t;
    }
    // row lists grouped by bi value 1..4
    for (int t = tid; t < TI; t += 256) {
        int c = bj_all[i0 + t];
        if (c > 0) { int p = atomicAdd(&rcnt[c - 1], 1); rlist[(c - 1) * 64 + p] = t; }
    }
    __syncthreads();

    const int n = tid & 63;
    const int g = tid >> 6;   // 0..3

    // ---------------- Phase A0: slot 0 for all 64 rows ----------------
    {
        const float* W0 = g_W + (size_t)h * DDIM * DDIM + n;   // c=0
        unsigned long long wp[32];
#pragma unroll
        for (int mb = 0; mb < 32; mb++)
            wp[mb] = pack2(W0[(2 * mb) * DDIM], W0[(2 * mb + 1) * DDIM]);
        for (int r = 0; r < 16; r++) {
            int i = g * 16 + r;
            const F4U* q4 = (const F4U*)(Qs + i * DDIM);
            unsigned long long acc = 0ull;
#pragma unroll
            for (int mb = 0; mb < 16; mb++) {
                F4U v = q4[mb];
                ffma2(acc, v.u[0], wp[2 * mb]);
                ffma2(acc, v.u[1], wp[2 * mb + 1]);
            }
            U64F2 r2; r2.u = acc;
            Us0[i * USTRD + n] = r2.f.x + r2.f.y;
        }
    }

    // ---------------- class passes ----------------
    const int tx = tid & 31, ty = tid >> 5;   // 32 x 8
    float* outbase = out + ((size_t)(b * HNUM + h) * SLEN + i0) * SLEN;

    for (int t = 0; t < 5; t++) {
        int nt  = jcnt[t];
        int off = joff[t];
        if (nt == 0) continue;

        if (t > 0) {
            // wait for previous pass's Ust readers, then recompute Ust for class t
            __syncthreads();
            int v   = g + 1;              // this group's bi value
            int cnt = rcnt[v - 1];
            if (cnt > 0) {
                int c = 4 * (v - 1) + t;  // 1..16
                const float* Wc = g_W + (size_t)(c * HNUM + h) * DDIM * DDIM + n;
                unsigned long long wp[32];
#pragma unroll
                for (int mb = 0; mb < 32; mb++)
                    wp[mb] = pack2(Wc[(2 * mb) * DDIM], Wc[(2 * mb + 1) * DDIM]);
                for (int r = 0; r < cnt; r++) {
                    int i = rlist[(v - 1) * 64 + r];
                    const F4U* q4 = (const F4U*)(Qs + i * DDIM);
                    unsigned long long acc = 0ull;
#pragma unroll
                    for (int mb = 0; mb < 16; mb++) {
                        F4U vq = q4[mb];
                        ffma2(acc, vq.u[0], wp[2 * mb]);
                        ffma2(acc, vq.u[1], wp[2 * mb + 1]);
                    }
                    U64F2 r2; r2.u = acc;
                    Ust[i * USTRD + n] = r2.f.x + r2.f.y;
                }
            }
        }

        for (int j0 = 0; j0 < nt; j0 += JT) {
            int chunk = nt - j0; if (chunk > JT) chunk = JT;
            __syncthreads();   // Ks reuse safety + Ust/Us0 visibility
            // gather K chunk rows (coalesced 256B rows)
            for (int x = tid; x < JT * 16; x += 256) {
                int r = x >> 4, mb = x & 15;
                float4 v;
                if (r < chunk) v = ((const float4*)(kbase + (size_t)jperm[off + j0 + r] * DDIM))[mb];
                else           v = make_float4(0.f, 0.f, 0.f, 0.f);
                *(float4*)(Ks + r * KSTR + mb * 4) = v;
            }
            __syncthreads();

            // register tile: 8 rows (stride 8) x 4 cols (stride 32), packed f32x2 accum
            unsigned long long acc[8][4];
#pragma unroll
            for (int ii = 0; ii < 8; ii++)
#pragma unroll
                for (int jj = 0; jj < 4; jj++) acc[ii][jj] = 0ull;

            const float* Arow[8];
#pragma unroll
            for (int ii = 0; ii < 8; ii++) {
                int i  = ty + ii * 8;
                int bi = bj_all[i0 + i];
                Arow[ii] = ((bi == 0 || t == 0) ? Us0 : Ust) + i * USTRD;
            }
#pragma unroll
            for (int mb = 0; mb < 16; mb++) {
                F4U kv[4];
#pragma unroll
                for (int jj = 0; jj < 4; jj++)
                    kv[jj].f4 = *(const float4*)(Ks + (tx + jj * 32) * KSTR + mb * 4);
#pragma unroll
                for (int ii = 0; ii < 8; ii++) {
                    F4U av;
                    av.f4 = *(const float4*)(Arow[ii] + mb * 4);
#pragma unroll
                    for (int jj = 0; jj < 4; jj++) {
                        ffma2(acc[ii][jj], av.u[0], kv[jj].u[0]);
                        ffma2(acc[ii][jj], av.u[1], kv[jj].u[1]);
                    }
                }
            }
            // scattered stores (L2 write-coalesced)
#pragma unroll
            for (int jj = 0; jj < 4; jj++) {
                int jc = tx + jj * 32;
                if (j0 + jc < nt) {
                    int jp = jperm[off + j0 + jc];
#pragma unroll
                    for (int ii = 0; ii < 8; ii++) {
                        U64F2 r2; r2.u = acc[ii][jj];
                        outbase[(size_t)(ty + ii * 8) * SLEN + jp] = r2.f.x + r2.f.y;
                    }
                }
            }
        }
    }
}

// ---------------- launch ----------------
extern "C" void kernel_launch(void* const* d_in, const int* in_sizes, int n_in,
                              void* d_out, int out_size) {
    const float* q      = (const float*)d_in[0];
    const float* kk     = (const float*)d_in[1];
    const int*   bseq   = (const int*)  d_in[2];
    const float* W1     = (const float*)d_in[3];
    const float* alpha1 = (const float*)d_in[4];
    float* out = (float*)d_out;

    cudaFuncSetAttribute(mb_scores_kernel,
                         cudaFuncAttributeMaxDynamicSharedMemorySize, SMEM_BYTES);

    dim3 g1(CNUM, HNUM);
    wmix_kernel<<<g1, 256>>>(W1, alpha1);

    dim3 g2(SLEN / TI, HNUM, BNUM);   // (8, 8, 8) = 512 blocks
    mb_scores_kernel<<<g2, 256, SMEM_BYTES>>>(q, kk, bseq, out);
}